// round 16
// baseline (speedup 1.0000x reference)
#include <cuda_runtime.h>
#include <cuda_bf16.h>
#include <cuda_fp16.h>
#include <math.h>
#include <stdint.h>

// Problem constants
#define T0 512
#define TT 2048
#define WIDTH 2048
#define NH 16
#define KH 4
#define HD 128
#define KC_BASE (TT*WIDTH)
#define VC_BASE (KC_BASE + TT*KH*HD)
#define NEGV -2.3819763e38f

// Scratch
__device__ float    g_qg[TT * NH * 256];
__device__ float    g_kraw[TT * KH * HD];
__device__ uint32_t g_qh[TT * NH * 64];       // q fp16 hd-pair packed
__device__ uint32_t g_kph[TT * 256];          // roped K fp16 hd-pair packed
__device__ uint32_t g_vph[(TT/2) * 512];      // V fp16 key-pair packed
__device__ __half   g_xh[TT * WIDTH];
__device__ __half   g_ench[TT * NH * HD];
__device__ uint32_t g_qgwp[2 * NH * 1024 * 256];
__device__ uint32_t g_kwp[2 * KH * 1024 * 128];
__device__ uint32_t g_vwp[2 * KH * 1024 * 128];
__device__ uint32_t g_owp[2 * 1024 * 2048];

// ---------------------------------------------------------------------------
// helpers
// ---------------------------------------------------------------------------
__device__ __forceinline__ uint32_t smem_u32(const void* p) {
    uint32_t a;
    asm("{ .reg .u64 t; cvta.to.shared.u64 t, %1; cvt.u32.u64 %0, t; }"
        : "=r"(a) : "l"(p));
    return a;
}

__device__ __forceinline__ void cpasync16(uint32_t s, const void* g) {
    asm volatile("cp.async.ca.shared.global [%0], [%1], 16;" :: "r"(s), "l"(g));
}
__device__ __forceinline__ void cpasync16cg(uint32_t s, const void* g) {
    asm volatile("cp.async.cg.shared.global [%0], [%1], 16;" :: "r"(s), "l"(g));
}

// fp16 m16n8k16 MMA, fp32 accumulate
__device__ __forceinline__ void mma16(float* c, const uint32_t* a, const uint32_t* b) {
    asm volatile(
        "mma.sync.aligned.m16n8k16.row.col.f32.f16.f16.f32 "
        "{%0,%1,%2,%3},{%4,%5,%6,%7},{%8,%9},{%0,%1,%2,%3};"
        : "+f"(c[0]), "+f"(c[1]), "+f"(c[2]), "+f"(c[3])
        : "r"(a[0]), "r"(a[1]), "r"(a[2]), "r"(a[3]), "r"(b[0]), "r"(b[1]));
}

__device__ __forceinline__ uint32_t packh2(float a, float b) {
    return (uint32_t)__half_as_ushort(__float2half_rn(a))
         | ((uint32_t)__half_as_ushort(__float2half_rn(b)) << 16);
}

// FMA-pipe exp (exp2 poly)
__device__ __forceinline__ float exp_poly(float x) {
    float xl = x * 1.4426950408889634f;
    xl = fmaxf(fminf(xl, 125.0f), -125.0f);
    float nf = rintf(xl);
    float fr = xl - nf;
    float t = fmaf(0.0096183425f, fr, 0.055503327f);
    t = fmaf(t, fr, 0.24022651f);
    t = fmaf(t, fr, 0.69314718f);
    t = fmaf(t, fr, 1.0f);
    return __uint_as_float(__float_as_uint(t) + (int)nf * 8388608);
}

// ---------------------------------------------------------------------------
// Pack x -> fp16, weights -> k-pair u32 [K/2][N]. grid.y = segment.
// ---------------------------------------------------------------------------
__global__ __launch_bounds__(256) void pack_kernel(
    const float* __restrict__ x0, const float* __restrict__ x1,
    const float* __restrict__ qgw0, const float* __restrict__ qgw1,
    const float* __restrict__ kw0, const float* __restrict__ kw1,
    const float* __restrict__ vw0, const float* __restrict__ vw1,
    const float* __restrict__ ow0, const float* __restrict__ ow1)
{
    const int seg = blockIdx.y;
    if (seg < 2) {
        const float* src = (seg == 0) ? x0 : x1;
        __half* dst = g_xh + ((seg == 0) ? 0 : T0 * WIDTH);
        const int n4 = ((seg == 0) ? T0 * WIDTH : (TT - T0) * WIDTH) >> 2;
        for (int i = blockIdx.x * 256 + threadIdx.x; i < n4; i += gridDim.x * 256) {
            float4 v = ((const float4*)src)[i];
            ((uint2*)dst)[i] = make_uint2(packh2(v.x, v.y), packh2(v.z, v.w));
        }
        return;
    }
    const float* src;
    uint32_t* dst;
    int Nb, nblk;
    switch (seg) {
        case 2: src = qgw0; dst = g_qgwp;                      Nb = 256;  nblk = NH; break;
        case 3: src = qgw1; dst = g_qgwp + NH * 1024 * 256;    Nb = 256;  nblk = NH; break;
        case 4: src = kw0;  dst = g_kwp;                       Nb = 128;  nblk = KH; break;
        case 5: src = kw1;  dst = g_kwp + KH * 1024 * 128;     Nb = 128;  nblk = KH; break;
        case 6: src = vw0;  dst = g_vwp;                       Nb = 128;  nblk = KH; break;
        case 7: src = vw1;  dst = g_vwp + KH * 1024 * 128;     Nb = 128;  nblk = KH; break;
        case 8: src = ow0;  dst = g_owp;                       Nb = 2048; nblk = 1; break;
        default: src = ow1; dst = g_owp + 1024 * 2048;         Nb = 2048; nblk = 1; break;
    }
    const int Kb = WIDTH;
    const int perblk = (Kb / 2) * (Nb / 4);
    const int total = nblk * perblk;
    for (int i = blockIdx.x * 256 + threadIdx.x; i < total; i += gridDim.x * 256) {
        const int blk = i / perblk;
        const int rem = i - blk * perblk;
        const int kp = rem / (Nb / 4);
        const int n4 = (rem - kp * (Nb / 4)) * 4;
        const float* s = src + (long)blk * Kb * Nb + (long)(2 * kp) * Nb + n4;
        float4 lo = *(const float4*)s;
        float4 hi = *(const float4*)(s + Nb);
        uint4 o;
        o.x = packh2(lo.x, hi.x);
        o.y = packh2(lo.y, hi.y);
        o.z = packh2(lo.z, hi.z);
        o.w = packh2(lo.w, hi.w);
        *(uint4*)(dst + (long)blk * (Kb / 2) * Nb + (long)kp * Nb + n4) = o;
    }
}

// V key-pair pack
__global__ __launch_bounds__(256) void vpack_kernel(const float* __restrict__ vc)
{
    int i = blockIdx.x * 256 + threadIdx.x;
    int tp = i >> 9;
    int c = i & 511;
    g_vph[i] = packh2(vc[(2 * tp) * 512 + c], vc[(2 * tp + 1) * 512 + c]);
}

// ---------------------------------------------------------------------------
// fp16 GEMM core (R14, unchanged)
// ---------------------------------------------------------------------------
#define ASTRH 20
#define BSTRH 136
#define A_STH (128 * ASTRH)
#define B_STH (8 * BSTRH)
#define ST_H (A_STH + B_STH)
#define GEMM_SMEM_BYTES (3 * ST_H * 4)

__device__ __forceinline__ void issue_stage_h(
    uint32_t sbase, int stage, const __half* A, int lda,
    const uint32_t* B, int ldb, int kt, int tid)
{
    const uint32_t aS = sbase + stage * (ST_H * 4);
    const uint32_t bS = aS + A_STH * 4;
    const int ar = tid >> 1;
    const int ah = tid & 1;
    cpasync16cg(aS + (ar * ASTRH + ah * 4) * 4, A + (long)ar * lda + kt * 16 + ah * 8);
    const int br = tid >> 5;
    const int bc = (tid & 31) * 4;
    cpasync16cg(bS + (br * BSTRH + bc) * 4, B + (long)(kt * 8 + br) * ldb + bc);
    asm volatile("cp.async.commit_group;" ::: "memory");
}

__device__ void gemm_h_core(
    const __half* __restrict__ A, int lda,
    const uint32_t* __restrict__ B, int ldb,
    float* __restrict__ C, int ldc, int Kdim)
{
    extern __shared__ float smf[];
    const uint32_t sbase = smem_u32(smf);
    const uint32_t* smU = (const uint32_t*)smf;

    const int tid = threadIdx.x;
    const int lane = tid & 31;
    const int g = lane >> 2;
    const int t = lane & 3;
    const int wid = tid >> 5;
    const int mw = (wid >> 1) * 32;
    const int nw = (wid & 1) * 64;

    const int nt = Kdim / 16;

    issue_stage_h(sbase, 0, A, lda, B, ldb, 0, tid);
    issue_stage_h(sbase, 1, A, lda, B, ldb, 1, tid);

    float acc[2][8][4] = {};

    for (int kt = 0; kt < nt; kt++) {
        if (kt + 2 < nt) {
            issue_stage_h(sbase, (kt + 2) % 3, A, lda, B, ldb, kt + 2, tid);
            asm volatile("cp.async.wait_group %0;" :: "n"(2) : "memory");
        } else if (kt + 1 < nt) {
            asm volatile("cp.async.wait_group %0;" :: "n"(1) : "memory");
        } else {
            asm volatile("cp.async.wait_group %0;" :: "n"(0) : "memory");
        }
        __syncthreads();

        const uint32_t* AsU = smU + (kt % 3) * ST_H;
        const uint32_t* BsU = AsU + A_STH;

        uint32_t afr[2][4], bfr[8][2];
        #pragma unroll
        for (int tm = 0; tm < 2; tm++) {
            const int mb = mw + tm * 16;
            afr[tm][0] = AsU[(mb + g)     * ASTRH + t];
            afr[tm][1] = AsU[(mb + g + 8) * ASTRH + t];
            afr[tm][2] = AsU[(mb + g)     * ASTRH + t + 4];
            afr[tm][3] = AsU[(mb + g + 8) * ASTRH + t + 4];
        }
        #pragma unroll
        for (int tn = 0; tn < 8; tn++) {
            const int nb = nw + tn * 8 + g;
            bfr[tn][0] = BsU[t       * BSTRH + nb];
            bfr[tn][1] = BsU[(t + 4) * BSTRH + nb];
        }
        #pragma unroll
        for (int tm = 0; tm < 2; tm++)
            #pragma unroll
            for (int tn = 0; tn < 8; tn++)
                mma16(acc[tm][tn], afr[tm], bfr[tn]);
        __syncthreads();
    }

    #pragma unroll
    for (int tm = 0; tm < 2; tm++) {
        #pragma unroll
        for (int tn = 0; tn < 8; tn++) {
            const int r0 = mw + tm * 16 + g;
            const int cc = nw + tn * 8 + 2 * t;
            *(float2*)&C[r0 * ldc + cc]       = make_float2(acc[tm][tn][0], acc[tm][tn][1]);
            *(float2*)&C[(r0 + 8) * ldc + cc] = make_float2(acc[tm][tn][2], acc[tm][tn][3]);
        }
    }
}

// Fused projections: qg (y 0..31), K (y 32..35), V (y 36..39). grid (16, 40).
__global__ __launch_bounds__(256, 2) void proj_fused_kernel(
    float* __restrict__ qg, float* __restrict__ kraw, float* __restrict__ vcache)
{
    const int tile = blockIdx.x;
    const int y = blockIdx.y;
    const __half* A = g_xh + (long)tile * 128 * WIDTH;
    const uint32_t* B;
    float* C;
    int ldb, ldc;
    if (y < 32) {
        const int n = y >> 1, bn = (y & 1) * 128;
        B = g_qgwp + ((tile < 4) ? 0 : (long)NH * 1024 * 256)
            + (long)n * 1024 * 256 + bn;
        ldb = 256;
        C = qg + (long)tile * 128 * (NH * 256) + n * 256 + bn;
        ldc = NH * 256;
    } else if (y < 36) {
        const int kk = y - 32;
        B = g_kwp + ((tile < 4) ? 0 : (long)KH * 1024 * 128) + (long)kk * 1024 * 128;
        ldb = 128;
        C = kraw + (long)tile * 128 * (KH * HD) + kk * HD;
        ldc = KH * HD;
    } else {
        const int kk = y - 36;
        B = g_vwp + ((tile < 4) ? 0 : (long)KH * 1024 * 128) + (long)kk * 1024 * 128;
        ldb = 128;
        C = vcache + (long)tile * 128 * (KH * HD) + kk * HD;
        ldc = KH * HD;
    }
    gemm_h_core(A, WIDTH, B, ldb, C, ldc, WIDTH);
}

// output projection: grid (16, 16)
__global__ __launch_bounds__(256, 2) void proj_out_kernel(float* __restrict__ out)
{
    const int tile = blockIdx.x;
    const int bn = blockIdx.y * 128;
    const __half* A = g_ench + (long)tile * 128 * (NH * HD);
    const uint32_t* B = g_owp + ((tile < 4) ? 0 : (long)1024 * 2048) + bn;
    float* C = out + (long)tile * 128 * WIDTH + bn;
    gemm_h_core(A, NH * HD, B, 2048, C, WIDTH, NH * HD);
}

// ---------------------------------------------------------------------------
// RMSNorm + RoPE (fp16 packed q/k emission)
// ---------------------------------------------------------------------------
__device__ __forceinline__ void emit_pair(uint32_t* dst, int col_base, int lane, float v) {
    float p = __shfl_down_sync(0xffffffffu, v, 1);
    if ((lane & 1) == 0) dst[col_base + (lane >> 1)] = packh2(v, p);
}

__global__ __launch_bounds__(128) void qnorm_rope(
    const float* __restrict__ qg, uint32_t* __restrict__ qh,
    const int* __restrict__ positions,
    const float* __restrict__ qn0, const float* __restrict__ qn1)
{
    int row  = blockIdx.x * 4 + (threadIdx.x >> 5);
    int lane = threadIdx.x & 31;
    int t = row >> 4;
    int n = row & 15;
    const float* src = qg + t * (NH * 256) + n * 256;

    float v0 = src[lane];
    float v1 = src[lane + 32];
    float v2 = src[lane + 64];
    float v3 = src[lane + 96];
    float ss = v0 * v0 + v1 * v1 + v2 * v2 + v3 * v3;
    #pragma unroll
    for (int o = 16; o; o >>= 1) ss += __shfl_xor_sync(0xffffffffu, ss, o);
    float inv = rsqrtf(ss * (1.0f / 128.0f) + 1e-6f);

    const float* qn = (t < T0) ? qn0 : qn1;
    v0 = v0 * inv * (1.0f + qn[lane]);
    v1 = v1 * inv * (1.0f + qn[lane + 32]);
    v2 = v2 * inv * (1.0f + qn[lane + 64]);
    v3 = v3 * inv * (1.0f + qn[lane + 96]);

    float p = (float)positions[t];
    float freq = powf(1000000.0f, -(float)lane / 32.0f);
    float s, c;
    sincosf(p * freq, &s, &c);

    const float SCL = 0.08838834764831845f;
    uint32_t* dst = qh + t * (NH * 64) + n * 64;
    emit_pair(dst, 0,  lane, (v0 * c - v1 * s) * SCL);
    emit_pair(dst, 16, lane, (v1 * c + v0 * s) * SCL);
    emit_pair(dst, 32, lane, v2 * SCL);
    emit_pair(dst, 48, lane, v3 * SCL);
}

__global__ __launch_bounds__(128) void knorm_rope(
    const float* __restrict__ kraw, float* __restrict__ kcache,
    uint32_t* __restrict__ kph,
    const int* __restrict__ positions,
    const float* __restrict__ kn0, const float* __restrict__ kn1)
{
    int row  = blockIdx.x * 4 + (threadIdx.x >> 5);
    int lane = threadIdx.x & 31;
    int t  = row >> 2;
    int kk = row & 3;
    const float* src = kraw + t * (KH * HD) + kk * HD;

    float v0 = src[lane];
    float v1 = src[lane + 32];
    float v2 = src[lane + 64];
    float v3 = src[lane + 96];
    float ss = v0 * v0 + v1 * v1 + v2 * v2 + v3 * v3;
    #pragma unroll
    for (int o = 16; o; o >>= 1) ss += __shfl_xor_sync(0xffffffffu, ss, o);
    float inv = rsqrtf(ss * (1.0f / 128.0f) + 1e-6f);

    const float* kn = (t < T0) ? kn0 : kn1;
    v0 = v0 * inv * (1.0f + kn[lane]);
    v1 = v1 * inv * (1.0f + kn[lane + 32]);
    v2 = v2 * inv * (1.0f + kn[lane + 64]);
    v3 = v3 * inv * (1.0f + kn[lane + 96]);

    float p = (float)positions[t];
    float freq = powf(1000000.0f, -(float)lane / 32.0f);
    float s, c;
    sincosf(p * freq, &s, &c);

    float r0 = v0 * c - v1 * s;
    float r1 = v1 * c + v0 * s;

    float* dst = kcache + t * (KH * HD) + kk * HD;
    dst[lane]      = r0;
    dst[lane + 32] = r1;
    dst[lane + 64] = v2;
    dst[lane + 96] = v3;

    uint32_t* dph = kph + t * 256 + kk * 64;
    emit_pair(dph, 0,  lane, r0);
    emit_pair(dph, 16, lane, r1);
    emit_pair(dph, 32, lane, v2);
    emit_pair(dph, 48, lane, v3);
}

// ---------------------------------------------------------------------------
// Flash attention fp16, 128-key blocks: 1 head x 64q per CTA, 128 threads,
// 2 CTAs/SM. Q in regs. K slot: 128 rows x 64 u32; V slot: 64 pair-rows x
// 128 u32 (both 32 KB, 3-slot rotation). Pw: [16][68] u32 per warp.
// ---------------------------------------------------------------------------
#define SLOT_U 8192
#define APW_OFF (3 * SLOT_U)
#define PSTRU 68
#define ATT_SMEM_U (APW_OFF + 4 * 16 * PSTRU)   // 28928 u32 = 115712 B

#define SWK(r, c) ((r) * 16 + ((c) ^ ((r) & 7)))
#define SWV(r, c) ((r) * 32 + ((c) ^ ((r) & 7)))

// stage K: 128 rows x 16 chunks (Q staging uses rows=64 variant below)
__device__ __forceinline__ void stage_k128(
    uint32_t sbase, int slot, const uint32_t* __restrict__ src, int lds,
    int row0, int tid)
{
    const uint32_t dst = sbase + slot * (SLOT_U * 4);
    #pragma unroll
    for (int i = 0; i < 16; i++) {
        const int lin = tid + 128 * i;
        const int r = lin >> 4;
        const int c = lin & 15;
        cpasync16(dst + SWK(r, c) * 16, src + (long)(row0 + r) * lds + c * 4);
    }
    asm volatile("cp.async.commit_group;" ::: "memory");
}

__device__ __forceinline__ void stage_q64(
    uint32_t sbase, int slot, const uint32_t* __restrict__ src, int lds,
    int row0, int tid)
{
    const uint32_t dst = sbase + slot * (SLOT_U * 4);
    #pragma unroll
    for (int i = 0; i < 8; i++) {
        const int lin = tid + 128 * i;
        const int r = lin >> 4;
        const int c = lin & 15;
        cpasync16(dst + SWK(r, c) * 16, src + (long)(row0 + r) * lds + c * 4);
    }
    asm volatile("cp.async.commit_group;" ::: "memory");
}

// stage V: 64 pair-rows x 32 chunks
__device__ __forceinline__ void stage_v(
    uint32_t sbase, int slot, const uint32_t* __restrict__ src, int rp0, int tid)
{
    const uint32_t dst = sbase + slot * (SLOT_U * 4);
    #pragma unroll
    for (int i = 0; i < 16; i++) {
        const int lin = tid + 128 * i;
        const int r = lin >> 5;
        const int c = lin & 31;
        cpasync16(dst + SWV(r, c) * 16, src + (long)(rp0 + r) * 512 + c * 4);
    }
    asm volatile("cp.async.commit_group;" ::: "memory");
}

__global__ __launch_bounds__(128, 2) void attn_kernel(
    const uint32_t* __restrict__ qh, const uint32_t* __restrict__ kph,
    const uint32_t* __restrict__ vph, const float* __restrict__ qg,
    __half* __restrict__ ench)
{
    extern __shared__ uint32_t smu[];
    const uint32_t sbase = smem_u32(smu);

    const int tid = threadIdx.x;
    const int lane = tid & 31;
    const int g = lane >> 2;
    const int t = lane & 3;
    const int wid = tid >> 5;
    const int mW = wid * 16;
    const int qt = gridDim.x - 1 - blockIdx.x;
    const int n = blockIdx.y;
    const int kvh = n >> 2;
    const int qbase = qt * 64;
    const int nb = (qbase + 64 + 127) >> 7;    // number of 128-key blocks

    uint32_t* Pw = smu + APW_OFF + wid * (16 * PSTRU);

    const uint32_t* kbase = kph + kvh * 64;      // row stride 256
    const uint32_t* vbase = vph + kvh * 128;     // pair-row stride 512

    // stage Q into slot 2, pull fragments into registers
    stage_q64(sbase, 2, qh + n * 64, NH * 64, qbase, tid);
    asm volatile("cp.async.wait_group 0;" ::: "memory");
    __syncthreads();

    uint32_t qreg[8][4];
    {
        const uint32_t* Qs = smu + 2 * SLOT_U;
        const int r0 = mW + g, r1 = r0 + 8;
        #pragma unroll
        for (int ks = 0; ks < 8; ks++) {
            qreg[ks][0] = Qs[SWK(r0, 2 * ks) * 4 + t];
            qreg[ks][1] = Qs[SWK(r1, 2 * ks) * 4 + t];
            qreg[ks][2] = Qs[SWK(r0, 2 * ks + 1) * 4 + t];
            qreg[ks][3] = Qs[SWK(r1, 2 * ks + 1) * 4 + t];
        }
    }
    __syncthreads();

    stage_k128(sbase, 0, kbase, 256, 0, tid);
    stage_v(sbase, 1, vbase, 0, tid);

    float m0 = -3.0e38f, m1 = -3.0e38f, l0 = 0.0f, l1 = 0.0f;
    float accO[16][4] = {};

    for (int j = 0; j < nb; j++) {
        const int nj = (j + 1 < nb) ? (j + 1) : (nb - 1);   // clamped prefetch

        // K(j) ready
        asm volatile("cp.async.wait_group %0;" :: "n"(1) : "memory");
        __syncthreads();

        stage_k128(sbase, (2 * j + 2) % 3, kbase, 256, nj * 128, tid);

        // ---- S = Q K^T: 16 rows x 128 keys (16 n-tiles, 8 k16-tiles) ----
        const uint32_t* Kf = smu + ((2 * j) % 3) * SLOT_U;
        float sacc[16][4] = {};
        #pragma unroll
        for (int ks = 0; ks < 8; ks++) {
            uint32_t bfr[16][2];
            #pragma unroll
            for (int tn = 0; tn < 16; tn++) {
                const int key = tn * 8 + g;
                bfr[tn][0] = Kf[SWK(key, 2 * ks) * 4 + t];
                bfr[tn][1] = Kf[SWK(key, 2 * ks + 1) * 4 + t];
            }
            #pragma unroll
            for (int tn = 0; tn < 16; tn++) mma16(sacc[tn], qreg[ks], bfr[tn]);
        }
        __syncthreads();

        stage_v(sbase, (2 * j) % 3, vbase, nj * 64, tid);

        // ---- causal mask (last block only) + register online softmax ----
        const int q0 = qbase + mW + g, q1 = q0 + 8;
        if (j == nb - 1) {
            const int kb = j * 128;
            #pragma unroll
            for (int tn = 0; tn < 16; tn++) {
                const int cc = kb + tn * 8 + 2 * t;
                if (cc     > q0) sacc[tn][0] = NEGV;
                if (cc + 1 > q0) sacc[tn][1] = NEGV;
                if (cc     > q1) sacc[tn][2] = NEGV;
                if (cc + 1 > q1) sacc[tn][3] = NEGV;
            }
        }
        float rmax0 = -3.0e38f, rmax1 = -3.0e38f;
        #pragma unroll
        for (int tn = 0; tn < 16; tn++) {
            rmax0 = fmaxf(rmax0, fmaxf(sacc[tn][0], sacc[tn][1]));
            rmax1 = fmaxf(rmax1, fmaxf(sacc[tn][2], sacc[tn][3]));
        }
        rmax0 = fmaxf(rmax0, __shfl_xor_sync(0xffffffffu, rmax0, 1));
        rmax0 = fmaxf(rmax0, __shfl_xor_sync(0xffffffffu, rmax0, 2));
        rmax1 = fmaxf(rmax1, __shfl_xor_sync(0xffffffffu, rmax1, 1));
        rmax1 = fmaxf(rmax1, __shfl_xor_sync(0xffffffffu, rmax1, 2));
        const float mn0 = fmaxf(m0, rmax0);
        const float mn1 = fmaxf(m1, rmax1);
        const float al0 = __expf(m0 - mn0);
        const float al1 = __expf(m1 - mn1);
        m0 = mn0; m1 = mn1;

        float sum0 = 0.0f, sum1 = 0.0f;
        #pragma unroll
        for (int tn = 0; tn < 16; tn++) {
            float p0, p1, p2, p3;
            if (tn & 1) {
                p0 = exp_poly(sacc[tn][0] - mn0); p1 = exp_poly(sacc[tn][1] - mn0);
                p2 = exp_poly(sacc[tn][2] - mn1); p3 = exp_poly(sacc[tn][3] - mn1);
            } else {
                p0 = __expf(sacc[tn][0] - mn0); p1 = __expf(sacc[tn][1] - mn0);
                p2 = __expf(sacc[tn][2] - mn1); p3 = __expf(sacc[tn][3] - mn1);
            }
            sum0 += p0 + p1;
            sum1 += p2 + p3;
            Pw[g * PSTRU + tn * 4 + t]       = packh2(p0, p1);
            Pw[(g + 8) * PSTRU + tn * 4 + t] = packh2(p2, p3);
        }
        sum0 += __shfl_xor_sync(0xffffffffu, sum0, 1);
        sum0 += __shfl_xor_sync(0xffffffffu, sum0, 2);
        sum1 += __shfl_xor_sync(0xffffffffu, sum1, 1);
        sum1 += __shfl_xor_sync(0xffffffffu, sum1, 2);
        l0 = l0 * al0 + sum0;
        l1 = l1 * al1 + sum1;

        #pragma unroll
        for (int tn = 0; tn < 16; tn++) {
            accO[tn][0] *= al0; accO[tn][1] *= al0;
            accO[tn][2] *= al1; accO[tn][3] *= al1;
        }

        // V(j) ready
        asm volatile("cp.async.wait_group %0;" :: "n"(2) : "memory");
        __syncthreads();

        // ---- O += P V: 8 k16-tiles over 128 keys ----
        const uint32_t* Vf = smu + ((2 * j + 1) % 3) * SLOT_U;
        #pragma unroll
        for (int ks = 0; ks < 8; ks++) {
            uint32_t afr[4], bfr[16][2];
            afr[0] = Pw[g * PSTRU + ks * 8 + t];
            afr[1] = Pw[(g + 8) * PSTRU + ks * 8 + t];
            afr[2] = Pw[g * PSTRU + ks * 8 + t + 4];
            afr[3] = Pw[(g + 8) * PSTRU + ks * 8 + t + 4];
            #pragma unroll
            for (int tn = 0; tn < 16; tn++) {
                const int ch = 2 * tn + (g >> 2);
                const int w = g & 3;
                bfr[tn][0] = Vf[SWV(ks * 8 + t,     ch) * 4 + w];
                bfr[tn][1] = Vf[SWV(ks * 8 + t + 4, ch) * 4 + w];
            }
            #pragma unroll
            for (int tn = 0; tn < 16; tn++) mma16(accO[tn], afr, bfr[tn]);
        }
    }

    asm volatile("cp.async.wait_group %0;" :: "n"(0) : "memory");

    // epilogue: 1/l scaling + fused sigmoid gate; store enc as fp16
    const int qr0 = qbase + mW + g;
    const int qr1 = qr0 + 8;
    const float inv0 = 1.0f / l0;
    const float inv1 = 1.0f / l1;
    #pragma unroll
    for (int tn = 0; tn < 16; tn++) {
        const int cc = tn * 8 + 2 * t;
        float2 gg0 = *(const float2*)&qg[qr0 * (NH * 256) + n * 256 + 128 + cc];
        float2 gg1 = *(const float2*)&qg[qr1 * (NH * 256) + n * 256 + 128 + cc];
        float e00, e01, e10, e11;
        if (tn & 1) {
            e00 = exp_poly(-gg0.x); e01 = exp_poly(-gg0.y);
            e10 = exp_poly(-gg1.x); e11 = exp_poly(-gg1.y);
        } else {
            e00 = __expf(-gg0.x); e01 = __expf(-gg0.y);
            e10 = __expf(-gg1.x); e11 = __expf(-gg1.y);
        }
        float s00 = 1.0f / (1.0f + e00);
        float s01 = 1.0f / (1.0f + e01);
        float s10 = 1.0f / (1.0f + e10);
        float s11 = 1.0f / (1.0f + e11);
        uint32_t* d0 = (uint32_t*)(ench + qr0 * (NH * HD) + n * HD + cc);
        uint32_t* d1 = (uint32_t*)(ench + qr1 * (NH * HD) + n * HD + cc);
        *d0 = packh2(accO[tn][0] * inv0 * s00, accO[tn][1] * inv0 * s01);
        *d1 = packh2(accO[tn][2] * inv1 * s10, accO[tn][3] * inv1 * s11);
    }
}

// ---------------------------------------------------------------------------
extern "C" void kernel_launch(void* const* d_in, const int* in_sizes, int n_in,
                              void* d_out, int out_size)
{
    const float* x0    = (const float*)d_in[0];
    const float* x1    = (const float*)d_in[1];
    const int*   pos   = (const int*)d_in[2];
    const float* qg_w0 = (const float*)d_in[4];
    const float* k_w0  = (const float*)d_in[5];
    const float* v_w0  = (const float*)d_in[6];
    const float* qn0   = (const float*)d_in[7];
    const float* kn0   = (const float*)d_in[8];
    const float* o_w0  = (const float*)d_in[9];
    const float* qg_w1 = (const float*)d_in[10];
    const float* k_w1  = (const float*)d_in[11];
    const float* v_w1  = (const float*)d_in[12];
    const float* qn1   = (const float*)d_in[13];
    const float* kn1   = (const float*)d_in[14];
    const float* o_w1  = (const float*)d_in[15];

    float* out = (float*)d_out;

    float *qg, *kraw;
    uint32_t *qh, *kph, *vph;
    __half* ench;
    cudaGetSymbolAddress((void**)&qg,   g_qg);
    cudaGetSymbolAddress((void**)&kraw, g_kraw);
    cudaGetSymbolAddress((void**)&qh,   g_qh);
    cudaGetSymbolAddress((void**)&kph,  g_kph);
    cudaGetSymbolAddress((void**)&vph,  g_vph);
    cudaGetSymbolAddress((void**)&ench, g_ench);

    cudaFuncSetAttribute(proj_fused_kernel, cudaFuncAttributeMaxDynamicSharedMemorySize, GEMM_SMEM_BYTES);
    cudaFuncSetAttribute(proj_out_kernel,   cudaFuncAttributeMaxDynamicSharedMemorySize, GEMM_SMEM_BYTES);
    cudaFuncSetAttribute(attn_kernel, cudaFuncAttributeMaxDynamicSharedMemorySize,
                         ATT_SMEM_U * sizeof(uint32_t));

    // pack x/weights
    pack_kernel<<<dim3(256, 10), 256>>>(x0, x1, qg_w0, qg_w1,
                                        k_w0, k_w1, v_w0, v_w1, o_w0, o_w1);

    // projections (fp16), V exact to d_out
    proj_fused_kernel<<<dim3(16, 40), 256, GEMM_SMEM_BYTES>>>(
        qg, kraw, out + VC_BASE);

    // V key-pair fp16 pack
    vpack_kernel<<<(TT/2)*512/256, 256>>>(out + VC_BASE);

    // norms + rope
    qnorm_rope<<<TT*NH/4, 128>>>(qg, qh, pos, qn0, qn1);
    knorm_rope<<<TT*KH/4, 128>>>(kraw, out + KC_BASE, kph, pos, kn0, kn1);

    // attention fp16, 128-key blocks
    attn_kernel<<<dim3(TT/64, NH), 128, ATT_SMEM_U * sizeof(uint32_t)>>>(
        qh, kph, vph, qg, ench);

    // output projection (fp16)
    proj_out_kernel<<<dim3(16, 16), 256, GEMM_SMEM_BYTES>>>(out);
}

// round 17
// speedup vs baseline: 1.0772x; 1.0772x over previous
#include <cuda_runtime.h>
#include <cuda_bf16.h>
#include <cuda_fp16.h>
#include <math.h>
#include <stdint.h>

// Problem constants
#define T0 512
#define TT 2048
#define WIDTH 2048
#define NH 16
#define KH 4
#define HD 128
#define KC_BASE (TT*WIDTH)
#define VC_BASE (KC_BASE + TT*KH*HD)
#define NEGV -2.3819763e38f

// Scratch
__device__ float    g_qg[TT * NH * 256];
__device__ float    g_kraw[TT * KH * HD];
__device__ uint32_t g_qh[TT * NH * 64];       // q fp16 hd-pair packed
__device__ uint32_t g_kph[TT * 256];          // roped K fp16 hd-pair packed
__device__ uint32_t g_vph[(TT/2) * 512];      // V fp16 key-pair packed
__device__ __half   g_xh[TT * WIDTH];
__device__ __half   g_ench[TT * NH * HD];
__device__ uint32_t g_qgwp[2 * NH * 1024 * 256];
__device__ uint32_t g_kwp[2 * KH * 1024 * 128];
__device__ uint32_t g_vwp[2 * KH * 1024 * 128];
__device__ uint32_t g_owp[2 * 1024 * 2048];

// ---------------------------------------------------------------------------
// helpers
// ---------------------------------------------------------------------------
__device__ __forceinline__ uint32_t smem_u32(const void* p) {
    uint32_t a;
    asm("{ .reg .u64 t; cvta.to.shared.u64 t, %1; cvt.u32.u64 %0, t; }"
        : "=r"(a) : "l"(p));
    return a;
}

__device__ __forceinline__ void cpasync16(uint32_t s, const void* g) {
    asm volatile("cp.async.ca.shared.global [%0], [%1], 16;" :: "r"(s), "l"(g));
}
__device__ __forceinline__ void cpasync16cg(uint32_t s, const void* g) {
    asm volatile("cp.async.cg.shared.global [%0], [%1], 16;" :: "r"(s), "l"(g));
}

// fp16 m16n8k16 MMA, fp32 accumulate
__device__ __forceinline__ void mma16(float* c, const uint32_t* a, const uint32_t* b) {
    asm volatile(
        "mma.sync.aligned.m16n8k16.row.col.f32.f16.f16.f32 "
        "{%0,%1,%2,%3},{%4,%5,%6,%7},{%8,%9},{%0,%1,%2,%3};"
        : "+f"(c[0]), "+f"(c[1]), "+f"(c[2]), "+f"(c[3])
        : "r"(a[0]), "r"(a[1]), "r"(a[2]), "r"(a[3]), "r"(b[0]), "r"(b[1]));
}

__device__ __forceinline__ uint32_t packh2(float a, float b) {
    return (uint32_t)__half_as_ushort(__float2half_rn(a))
         | ((uint32_t)__half_as_ushort(__float2half_rn(b)) << 16);
}

// FMA-pipe exp (exp2 poly)
__device__ __forceinline__ float exp_poly(float x) {
    float xl = x * 1.4426950408889634f;
    xl = fmaxf(fminf(xl, 125.0f), -125.0f);
    float nf = rintf(xl);
    float fr = xl - nf;
    float t = fmaf(0.0096183425f, fr, 0.055503327f);
    t = fmaf(t, fr, 0.24022651f);
    t = fmaf(t, fr, 0.69314718f);
    t = fmaf(t, fr, 1.0f);
    return __uint_as_float(__float_as_uint(t) + (int)nf * 8388608);
}

// ---------------------------------------------------------------------------
// Pack x -> fp16, weights -> k-pair u32 [K/2][N]. grid.y = segment.
// ---------------------------------------------------------------------------
__global__ __launch_bounds__(256) void pack_kernel(
    const float* __restrict__ x0, const float* __restrict__ x1,
    const float* __restrict__ qgw0, const float* __restrict__ qgw1,
    const float* __restrict__ kw0, const float* __restrict__ kw1,
    const float* __restrict__ vw0, const float* __restrict__ vw1,
    const float* __restrict__ ow0, const float* __restrict__ ow1)
{
    const int seg = blockIdx.y;
    if (seg < 2) {
        const float* src = (seg == 0) ? x0 : x1;
        __half* dst = g_xh + ((seg == 0) ? 0 : T0 * WIDTH);
        const int n4 = ((seg == 0) ? T0 * WIDTH : (TT - T0) * WIDTH) >> 2;
        for (int i = blockIdx.x * 256 + threadIdx.x; i < n4; i += gridDim.x * 256) {
            float4 v = ((const float4*)src)[i];
            ((uint2*)dst)[i] = make_uint2(packh2(v.x, v.y), packh2(v.z, v.w));
        }
        return;
    }
    const float* src;
    uint32_t* dst;
    int Nb, nblk;
    switch (seg) {
        case 2: src = qgw0; dst = g_qgwp;                      Nb = 256;  nblk = NH; break;
        case 3: src = qgw1; dst = g_qgwp + NH * 1024 * 256;    Nb = 256;  nblk = NH; break;
        case 4: src = kw0;  dst = g_kwp;                       Nb = 128;  nblk = KH; break;
        case 5: src = kw1;  dst = g_kwp + KH * 1024 * 128;     Nb = 128;  nblk = KH; break;
        case 6: src = vw0;  dst = g_vwp;                       Nb = 128;  nblk = KH; break;
        case 7: src = vw1;  dst = g_vwp + KH * 1024 * 128;     Nb = 128;  nblk = KH; break;
        case 8: src = ow0;  dst = g_owp;                       Nb = 2048; nblk = 1; break;
        default: src = ow1; dst = g_owp + 1024 * 2048;         Nb = 2048; nblk = 1; break;
    }
    const int Kb = WIDTH;
    const int perblk = (Kb / 2) * (Nb / 4);
    const int total = nblk * perblk;
    for (int i = blockIdx.x * 256 + threadIdx.x; i < total; i += gridDim.x * 256) {
        const int blk = i / perblk;
        const int rem = i - blk * perblk;
        const int kp = rem / (Nb / 4);
        const int n4 = (rem - kp * (Nb / 4)) * 4;
        const float* s = src + (long)blk * Kb * Nb + (long)(2 * kp) * Nb + n4;
        float4 lo = *(const float4*)s;
        float4 hi = *(const float4*)(s + Nb);
        uint4 o;
        o.x = packh2(lo.x, hi.x);
        o.y = packh2(lo.y, hi.y);
        o.z = packh2(lo.z, hi.z);
        o.w = packh2(lo.w, hi.w);
        *(uint4*)(dst + (long)blk * (Kb / 2) * Nb + (long)kp * Nb + n4) = o;
    }
}

// ---------------------------------------------------------------------------
// fp16 GEMM core. isV: epilogue also emits key-pair fp16 V into g_vph.
// ---------------------------------------------------------------------------
#define ASTRH 20
#define BSTRH 136
#define A_STH (128 * ASTRH)
#define B_STH (8 * BSTRH)
#define ST_H (A_STH + B_STH)
#define GEMM_SMEM_BYTES (3 * ST_H * 4)

__device__ __forceinline__ void issue_stage_h(
    uint32_t sbase, int stage, const __half* A, int lda,
    const uint32_t* B, int ldb, int kt, int tid)
{
    const uint32_t aS = sbase + stage * (ST_H * 4);
    const uint32_t bS = aS + A_STH * 4;
    const int ar = tid >> 1;
    const int ah = tid & 1;
    cpasync16cg(aS + (ar * ASTRH + ah * 4) * 4, A + (long)ar * lda + kt * 16 + ah * 8);
    const int br = tid >> 5;
    const int bc = (tid & 31) * 4;
    cpasync16cg(bS + (br * BSTRH + bc) * 4, B + (long)(kt * 8 + br) * ldb + bc);
    asm volatile("cp.async.commit_group;" ::: "memory");
}

__device__ void gemm_h_core(
    const __half* __restrict__ A, int lda,
    const uint32_t* __restrict__ B, int ldb,
    float* __restrict__ C, int ldc, int Kdim,
    uint32_t* __restrict__ vph_dst /* nullptr unless V block */, int vrow0, int vcol0)
{
    extern __shared__ float smf[];
    const uint32_t sbase = smem_u32(smf);
    const uint32_t* smU = (const uint32_t*)smf;

    const int tid = threadIdx.x;
    const int lane = tid & 31;
    const int g = lane >> 2;
    const int t = lane & 3;
    const int wid = tid >> 5;
    const int mw = (wid >> 1) * 32;
    const int nw = (wid & 1) * 64;

    const int nt = Kdim / 16;

    issue_stage_h(sbase, 0, A, lda, B, ldb, 0, tid);
    issue_stage_h(sbase, 1, A, lda, B, ldb, 1, tid);

    float acc[2][8][4] = {};

    for (int kt = 0; kt < nt; kt++) {
        if (kt + 2 < nt) {
            issue_stage_h(sbase, (kt + 2) % 3, A, lda, B, ldb, kt + 2, tid);
            asm volatile("cp.async.wait_group %0;" :: "n"(2) : "memory");
        } else if (kt + 1 < nt) {
            asm volatile("cp.async.wait_group %0;" :: "n"(1) : "memory");
        } else {
            asm volatile("cp.async.wait_group %0;" :: "n"(0) : "memory");
        }
        __syncthreads();

        const uint32_t* AsU = smU + (kt % 3) * ST_H;
        const uint32_t* BsU = AsU + A_STH;

        uint32_t afr[2][4], bfr[8][2];
        #pragma unroll
        for (int tm = 0; tm < 2; tm++) {
            const int mb = mw + tm * 16;
            afr[tm][0] = AsU[(mb + g)     * ASTRH + t];
            afr[tm][1] = AsU[(mb + g + 8) * ASTRH + t];
            afr[tm][2] = AsU[(mb + g)     * ASTRH + t + 4];
            afr[tm][3] = AsU[(mb + g + 8) * ASTRH + t + 4];
        }
        #pragma unroll
        for (int tn = 0; tn < 8; tn++) {
            const int nb = nw + tn * 8 + g;
            bfr[tn][0] = BsU[t       * BSTRH + nb];
            bfr[tn][1] = BsU[(t + 4) * BSTRH + nb];
        }
        #pragma unroll
        for (int tm = 0; tm < 2; tm++)
            #pragma unroll
            for (int tn = 0; tn < 8; tn++)
                mma16(acc[tm][tn], afr[tm], bfr[tn]);
        __syncthreads();
    }

    #pragma unroll
    for (int tm = 0; tm < 2; tm++) {
        #pragma unroll
        for (int tn = 0; tn < 8; tn++) {
            const int r0 = mw + tm * 16 + g;
            const int cc = nw + tn * 8 + 2 * t;
            *(float2*)&C[r0 * ldc + cc]       = make_float2(acc[tm][tn][0], acc[tm][tn][1]);
            *(float2*)&C[(r0 + 8) * ldc + cc] = make_float2(acc[tm][tn][2], acc[tm][tn][3]);
        }
    }

    // V epilogue: emit fp16 key-pair pack (pairs of adjacent token rows).
    // Row r0 = mw+tm*16+g: even g pairs with g+1 (lane+4) via shfl.
    if (vph_dst) {
        #pragma unroll
        for (int tm = 0; tm < 2; tm++) {
            #pragma unroll
            for (int tn = 0; tn < 8; tn++) {
                const int r0 = mw + tm * 16 + g;
                const int cc = nw + tn * 8 + 2 * t;
                float a0 = acc[tm][tn][0], a1 = acc[tm][tn][1];
                float a2 = acc[tm][tn][2], a3 = acc[tm][tn][3];
                float b0 = __shfl_down_sync(0xffffffffu, a0, 4);
                float b1 = __shfl_down_sync(0xffffffffu, a1, 4);
                float b2 = __shfl_down_sync(0xffffffffu, a2, 4);
                float b3 = __shfl_down_sync(0xffffffffu, a3, 4);
                if ((g & 1) == 0) {
                    const int tp0 = (vrow0 + r0) >> 1;
                    const int tp1 = (vrow0 + r0 + 8) >> 1;
                    uint32_t* d0 = vph_dst + (long)tp0 * 512 + vcol0 + cc;
                    uint32_t* d1 = vph_dst + (long)tp1 * 512 + vcol0 + cc;
                    d0[0] = packh2(a0, b0); d0[1] = packh2(a1, b1);
                    d1[0] = packh2(a2, b2); d1[1] = packh2(a3, b3);
                }
            }
        }
    }
}

// Fused projections: qg (y 0..31), K (y 32..35), V (y 36..39). grid (16, 40).
__global__ __launch_bounds__(256, 2) void proj_fused_kernel(
    float* __restrict__ qg, float* __restrict__ kraw, float* __restrict__ vcache,
    uint32_t* __restrict__ vph)
{
    const int tile = blockIdx.x;
    const int y = blockIdx.y;
    const __half* A = g_xh + (long)tile * 128 * WIDTH;
    const uint32_t* B;
    float* C;
    int ldb, ldc;
    uint32_t* vdst = nullptr;
    int vrow0 = 0, vcol0 = 0;
    if (y < 32) {
        const int n = y >> 1, bn = (y & 1) * 128;
        B = g_qgwp + ((tile < 4) ? 0 : (long)NH * 1024 * 256)
            + (long)n * 1024 * 256 + bn;
        ldb = 256;
        C = qg + (long)tile * 128 * (NH * 256) + n * 256 + bn;
        ldc = NH * 256;
    } else if (y < 36) {
        const int kk = y - 32;
        B = g_kwp + ((tile < 4) ? 0 : (long)KH * 1024 * 128) + (long)kk * 1024 * 128;
        ldb = 128;
        C = kraw + (long)tile * 128 * (KH * HD) + kk * HD;
        ldc = KH * HD;
    } else {
        const int kk = y - 36;
        B = g_vwp + ((tile < 4) ? 0 : (long)KH * 1024 * 128) + (long)kk * 1024 * 128;
        ldb = 128;
        C = vcache + (long)tile * 128 * (KH * HD) + kk * HD;
        ldc = KH * HD;
        vdst = vph;
        vrow0 = tile * 128;
        vcol0 = kk * HD;
    }
    gemm_h_core(A, WIDTH, B, ldb, C, ldc, WIDTH, vdst, vrow0, vcol0);
}

// output projection: grid (16, 16)
__global__ __launch_bounds__(256, 2) void proj_out_kernel(float* __restrict__ out)
{
    const int tile = blockIdx.x;
    const int bn = blockIdx.y * 128;
    const __half* A = g_ench + (long)tile * 128 * (NH * HD);
    const uint32_t* B = g_owp + ((tile < 4) ? 0 : (long)1024 * 2048) + bn;
    float* C = out + (long)tile * 128 * WIDTH + bn;
    gemm_h_core(A, NH * HD, B, 2048, C, WIDTH, NH * HD, nullptr, 0, 0);
}

// ---------------------------------------------------------------------------
// RMSNorm + RoPE (fp16 packed q/k emission)
// ---------------------------------------------------------------------------
__device__ __forceinline__ void emit_pair(uint32_t* dst, int col_base, int lane, float v) {
    float p = __shfl_down_sync(0xffffffffu, v, 1);
    if ((lane & 1) == 0) dst[col_base + (lane >> 1)] = packh2(v, p);
}

__global__ __launch_bounds__(128) void qnorm_rope(
    const float* __restrict__ qg, uint32_t* __restrict__ qh,
    const int* __restrict__ positions,
    const float* __restrict__ qn0, const float* __restrict__ qn1)
{
    int row  = blockIdx.x * 4 + (threadIdx.x >> 5);
    int lane = threadIdx.x & 31;
    int t = row >> 4;
    int n = row & 15;
    const float* src = qg + t * (NH * 256) + n * 256;

    float v0 = src[lane];
    float v1 = src[lane + 32];
    float v2 = src[lane + 64];
    float v3 = src[lane + 96];
    float ss = v0 * v0 + v1 * v1 + v2 * v2 + v3 * v3;
    #pragma unroll
    for (int o = 16; o; o >>= 1) ss += __shfl_xor_sync(0xffffffffu, ss, o);
    float inv = rsqrtf(ss * (1.0f / 128.0f) + 1e-6f);

    const float* qn = (t < T0) ? qn0 : qn1;
    v0 = v0 * inv * (1.0f + qn[lane]);
    v1 = v1 * inv * (1.0f + qn[lane + 32]);
    v2 = v2 * inv * (1.0f + qn[lane + 64]);
    v3 = v3 * inv * (1.0f + qn[lane + 96]);

    float p = (float)positions[t];
    float freq = powf(1000000.0f, -(float)lane / 32.0f);
    float s, c;
    sincosf(p * freq, &s, &c);

    const float SCL = 0.08838834764831845f;
    uint32_t* dst = qh + t * (NH * 64) + n * 64;
    emit_pair(dst, 0,  lane, (v0 * c - v1 * s) * SCL);
    emit_pair(dst, 16, lane, (v1 * c + v0 * s) * SCL);
    emit_pair(dst, 32, lane, v2 * SCL);
    emit_pair(dst, 48, lane, v3 * SCL);
}

__global__ __launch_bounds__(128) void knorm_rope(
    const float* __restrict__ kraw, float* __restrict__ kcache,
    uint32_t* __restrict__ kph,
    const int* __restrict__ positions,
    const float* __restrict__ kn0, const float* __restrict__ kn1)
{
    int row  = blockIdx.x * 4 + (threadIdx.x >> 5);
    int lane = threadIdx.x & 31;
    int t  = row >> 2;
    int kk = row & 3;
    const float* src = kraw + t * (KH * HD) + kk * HD;

    float v0 = src[lane];
    float v1 = src[lane + 32];
    float v2 = src[lane + 64];
    float v3 = src[lane + 96];
    float ss = v0 * v0 + v1 * v1 + v2 * v2 + v3 * v3;
    #pragma unroll
    for (int o = 16; o; o >>= 1) ss += __shfl_xor_sync(0xffffffffu, ss, o);
    float inv = rsqrtf(ss * (1.0f / 128.0f) + 1e-6f);

    const float* kn = (t < T0) ? kn0 : kn1;
    v0 = v0 * inv * (1.0f + kn[lane]);
    v1 = v1 * inv * (1.0f + kn[lane + 32]);
    v2 = v2 * inv * (1.0f + kn[lane + 64]);
    v3 = v3 * inv * (1.0f + kn[lane + 96]);

    float p = (float)positions[t];
    float freq = powf(1000000.0f, -(float)lane / 32.0f);
    float s, c;
    sincosf(p * freq, &s, &c);

    float r0 = v0 * c - v1 * s;
    float r1 = v1 * c + v0 * s;

    float* dst = kcache + t * (KH * HD) + kk * HD;
    dst[lane]      = r0;
    dst[lane + 32] = r1;
    dst[lane + 64] = v2;
    dst[lane + 96] = v3;

    uint32_t* dph = kph + t * 256 + kk * 64;
    emit_pair(dph, 0,  lane, r0);
    emit_pair(dph, 16, lane, r1);
    emit_pair(dph, 32, lane, v2);
    emit_pair(dph, 48, lane, v3);
}

// ---------------------------------------------------------------------------
// Flash attention fp16 (R15 geometry): 1 head x 64q per CTA, 128 threads,
// 3 CTAs/SM. Q in regs. K slot: 64 rows x 64 u32; V slot: 32 pair-rows x
// 128 u32 (16 KB each, 3-slot rotation). Pw: [16][36] u32 per warp.
// ---------------------------------------------------------------------------
#define SLOT_U 4096
#define APW_OFF (3 * SLOT_U)
#define ATT_SMEM_U (APW_OFF + 4 * 16 * 36)    // 14592 u32 = 58368 B

#define SWK(r, c) ((r) * 16 + ((c) ^ ((r) & 7)))
#define SWV(r, c) ((r) * 32 + ((c) ^ ((r) & 7)))

__device__ __forceinline__ void stage_k(
    uint32_t sbase, int slot, const uint32_t* __restrict__ src, int lds,
    int row0, int tid)
{
    const uint32_t dst = sbase + slot * (SLOT_U * 4);
    #pragma unroll
    for (int i = 0; i < 8; i++) {
        const int lin = tid + 128 * i;
        const int r = lin >> 4;
        const int c = lin & 15;
        cpasync16(dst + SWK(r, c) * 16, src + (long)(row0 + r) * lds + c * 4);
    }
    asm volatile("cp.async.commit_group;" ::: "memory");
}

__device__ __forceinline__ void stage_v(
    uint32_t sbase, int slot, const uint32_t* __restrict__ src, int rp0, int tid)
{
    const uint32_t dst = sbase + slot * (SLOT_U * 4);
    #pragma unroll
    for (int i = 0; i < 8; i++) {
        const int lin = tid + 128 * i;
        const int r = lin >> 5;
        const int c = lin & 31;
        cpasync16(dst + SWV(r, c) * 16, src + (long)(rp0 + r) * 512 + c * 4);
    }
    asm volatile("cp.async.commit_group;" ::: "memory");
}

__global__ __launch_bounds__(128, 3) void attn_kernel(
    const uint32_t* __restrict__ qh, const uint32_t* __restrict__ kph,
    const uint32_t* __restrict__ vph, const float* __restrict__ qg,
    __half* __restrict__ ench)
{
    extern __shared__ uint32_t smu[];
    const uint32_t sbase = smem_u32(smu);

    const int tid = threadIdx.x;
    const int lane = tid & 31;
    const int g = lane >> 2;
    const int t = lane & 3;
    const int wid = tid >> 5;
    const int mW = wid * 16;
    const int qt = gridDim.x - 1 - blockIdx.x;
    const int n = blockIdx.y;
    const int kvh = n >> 2;
    const int qbase = qt * 64;

    uint32_t* Pw = smu + APW_OFF + wid * (16 * 36);

    const uint32_t* kbase = kph + kvh * 64;      // row stride 256
    const uint32_t* vbase = vph + kvh * 128;     // pair-row stride 512

    // stage Q into slot 2, pull fragments into registers
    stage_k(sbase, 2, qh + n * 64, NH * 64, qbase, tid);
    asm volatile("cp.async.wait_group 0;" ::: "memory");
    __syncthreads();

    uint32_t qreg[8][4];
    {
        const uint32_t* Qs = smu + 2 * SLOT_U;
        const int r0 = mW + g, r1 = r0 + 8;
        #pragma unroll
        for (int ks = 0; ks < 8; ks++) {
            qreg[ks][0] = Qs[SWK(r0, 2 * ks) * 4 + t];
            qreg[ks][1] = Qs[SWK(r1, 2 * ks) * 4 + t];
            qreg[ks][2] = Qs[SWK(r0, 2 * ks + 1) * 4 + t];
            qreg[ks][3] = Qs[SWK(r1, 2 * ks + 1) * 4 + t];
        }
    }
    __syncthreads();

    stage_k(sbase, 0, kbase, 256, 0, tid);
    stage_v(sbase, 1, vbase, 0, tid);

    float m0 = -3.0e38f, m1 = -3.0e38f, l0 = 0.0f, l1 = 0.0f;
    float accO[16][4] = {};

    for (int j = 0; j <= qt; j++) {
        const int nsb = (j + 1 <= qt) ? (j + 1) * 64 : qt * 64;

        asm volatile("cp.async.wait_group %0;" :: "n"(1) : "memory");
        __syncthreads();

        stage_k(sbase, (2 * j + 2) % 3, kbase, 256, nsb, tid);

        // ---- S = Q K^T: 16 rows x 64 keys, 8 k16-tiles ----
        const uint32_t* Kf = smu + ((2 * j) % 3) * SLOT_U;
        float sacc[8][4] = {};
        #pragma unroll
        for (int ks = 0; ks < 8; ks++) {
            uint32_t bfr[8][2];
            #pragma unroll
            for (int tn = 0; tn < 8; tn++) {
                const int key = tn * 8 + g;
                bfr[tn][0] = Kf[SWK(key, 2 * ks) * 4 + t];
                bfr[tn][1] = Kf[SWK(key, 2 * ks + 1) * 4 + t];
            }
            #pragma unroll
            for (int tn = 0; tn < 8; tn++) mma16(sacc[tn], qreg[ks], bfr[tn]);
        }
        __syncthreads();

        stage_v(sbase, (2 * j) % 3, vbase, nsb >> 1, tid);

        // ---- causal mask + register online softmax ----
        const int q0 = mW + g, q1 = mW + g + 8;
        if (j == qt) {
            #pragma unroll
            for (int tn = 0; tn < 8; tn++) {
                const int cc = tn * 8 + 2 * t;
                if (cc     > q0) sacc[tn][0] = NEGV;
                if (cc + 1 > q0) sacc[tn][1] = NEGV;
                if (cc     > q1) sacc[tn][2] = NEGV;
                if (cc + 1 > q1) sacc[tn][3] = NEGV;
            }
        }
        float rmax0 = -3.0e38f, rmax1 = -3.0e38f;
        #pragma unroll
        for (int tn = 0; tn < 8; tn++) {
            rmax0 = fmaxf(rmax0, fmaxf(sacc[tn][0], sacc[tn][1]));
            rmax1 = fmaxf(rmax1, fmaxf(sacc[tn][2], sacc[tn][3]));
        }
        rmax0 = fmaxf(rmax0, __shfl_xor_sync(0xffffffffu, rmax0, 1));
        rmax0 = fmaxf(rmax0, __shfl_xor_sync(0xffffffffu, rmax0, 2));
        rmax1 = fmaxf(rmax1, __shfl_xor_sync(0xffffffffu, rmax1, 1));
        rmax1 = fmaxf(rmax1, __shfl_xor_sync(0xffffffffu, rmax1, 2));
        const float mn0 = fmaxf(m0, rmax0);
        const float mn1 = fmaxf(m1, rmax1);
        const float al0 = __expf(m0 - mn0);
        const float al1 = __expf(m1 - mn1);
        m0 = mn0; m1 = mn1;

        float sum0 = 0.0f, sum1 = 0.0f;
        #pragma unroll
        for (int tn = 0; tn < 8; tn++) {
            float p0, p1, p2, p3;
            if (tn & 1) {
                p0 = exp_poly(sacc[tn][0] - mn0); p1 = exp_poly(sacc[tn][1] - mn0);
                p2 = exp_poly(sacc[tn][2] - mn1); p3 = exp_poly(sacc[tn][3] - mn1);
            } else {
                p0 = __expf(sacc[tn][0] - mn0); p1 = __expf(sacc[tn][1] - mn0);
                p2 = __expf(sacc[tn][2] - mn1); p3 = __expf(sacc[tn][3] - mn1);
            }
            sum0 += p0 + p1;
            sum1 += p2 + p3;
            Pw[g * 36 + tn * 4 + t]       = packh2(p0, p1);
            Pw[(g + 8) * 36 + tn * 4 + t] = packh2(p2, p3);
        }
        sum0 += __shfl_xor_sync(0xffffffffu, sum0, 1);
        sum0 += __shfl_xor_sync(0xffffffffu, sum0, 2);
        sum1 += __shfl_xor_sync(0xffffffffu, sum1, 1);
        sum1 += __shfl_xor_sync(0xffffffffu, sum1, 2);
        l0 = l0 * al0 + sum0;
        l1 = l1 * al1 + sum1;

        #pragma unroll
        for (int tn = 0; tn < 16; tn++) {
            accO[tn][0] *= al0; accO[tn][1] *= al0;
            accO[tn][2] *= al1; accO[tn][3] *= al1;
        }

        asm volatile("cp.async.wait_group %0;" :: "n"(2) : "memory");
        __syncthreads();

        // ---- O += P V: 4 k16-tiles over 64 keys ----
        const uint32_t* Vf = smu + ((2 * j + 1) % 3) * SLOT_U;
        #pragma unroll
        for (int ks = 0; ks < 4; ks++) {
            uint32_t afr[4], bfr[16][2];
            afr[0] = Pw[g * 36 + ks * 8 + t];
            afr[1] = Pw[(g + 8) * 36 + ks * 8 + t];
            afr[2] = Pw[g * 36 + ks * 8 + t + 4];
            afr[3] = Pw[(g + 8) * 36 + ks * 8 + t + 4];
            #pragma unroll
            for (int tn = 0; tn < 16; tn++) {
                const int ch = 2 * tn + (g >> 2);
                const int w = g & 3;
                bfr[tn][0] = Vf[SWV(ks * 8 + t,     ch) * 4 + w];
                bfr[tn][1] = Vf[SWV(ks * 8 + t + 4, ch) * 4 + w];
            }
            #pragma unroll
            for (int tn = 0; tn < 16; tn++) mma16(accO[tn], afr, bfr[tn]);
        }
    }

    asm volatile("cp.async.wait_group %0;" :: "n"(0) : "memory");

    // epilogue: 1/l scaling + fused sigmoid gate; store enc as fp16
    const int qr0 = qbase + mW + g;
    const int qr1 = qr0 + 8;
    const float inv0 = 1.0f / l0;
    const float inv1 = 1.0f / l1;
    #pragma unroll
    for (int tn = 0; tn < 16; tn++) {
        const int cc = tn * 8 + 2 * t;
        float2 gg0 = *(const float2*)&qg[qr0 * (NH * 256) + n * 256 + 128 + cc];
        float2 gg1 = *(const float2*)&qg[qr1 * (NH * 256) + n * 256 + 128 + cc];
        float e00, e01, e10, e11;
        if (tn & 1) {
            e00 = exp_poly(-gg0.x); e01 = exp_poly(-gg0.y);
            e10 = exp_poly(-gg1.x); e11 = exp_poly(-gg1.y);
        } else {
            e00 = __expf(-gg0.x); e01 = __expf(-gg0.y);
            e10 = __expf(-gg1.x); e11 = __expf(-gg1.y);
        }
        float s00 = 1.0f / (1.0f + e00);
        float s01 = 1.0f / (1.0f + e01);
        float s10 = 1.0f / (1.0f + e10);
        float s11 = 1.0f / (1.0f + e11);
        uint32_t* d0 = (uint32_t*)(ench + qr0 * (NH * HD) + n * HD + cc);
        uint32_t* d1 = (uint32_t*)(ench + qr1 * (NH * HD) + n * HD + cc);
        *d0 = packh2(accO[tn][0] * inv0 * s00, accO[tn][1] * inv0 * s01);
        *d1 = packh2(accO[tn][2] * inv1 * s10, accO[tn][3] * inv1 * s11);
    }
}

// ---------------------------------------------------------------------------
extern "C" void kernel_launch(void* const* d_in, const int* in_sizes, int n_in,
                              void* d_out, int out_size)
{
    const float* x0    = (const float*)d_in[0];
    const float* x1    = (const float*)d_in[1];
    const int*   pos   = (const int*)d_in[2];
    const float* qg_w0 = (const float*)d_in[4];
    const float* k_w0  = (const float*)d_in[5];
    const float* v_w0  = (const float*)d_in[6];
    const float* qn0   = (const float*)d_in[7];
    const float* kn0   = (const float*)d_in[8];
    const float* o_w0  = (const float*)d_in[9];
    const float* qg_w1 = (const float*)d_in[10];
    const float* k_w1  = (const float*)d_in[11];
    const float* v_w1  = (const float*)d_in[12];
    const float* qn1   = (const float*)d_in[13];
    const float* kn1   = (const float*)d_in[14];
    const float* o_w1  = (const float*)d_in[15];

    float* out = (float*)d_out;

    float *qg, *kraw;
    uint32_t *qh, *kph, *vph;
    __half* ench;
    cudaGetSymbolAddress((void**)&qg,   g_qg);
    cudaGetSymbolAddress((void**)&kraw, g_kraw);
    cudaGetSymbolAddress((void**)&qh,   g_qh);
    cudaGetSymbolAddress((void**)&kph,  g_kph);
    cudaGetSymbolAddress((void**)&vph,  g_vph);
    cudaGetSymbolAddress((void**)&ench, g_ench);

    cudaFuncSetAttribute(proj_fused_kernel, cudaFuncAttributeMaxDynamicSharedMemorySize, GEMM_SMEM_BYTES);
    cudaFuncSetAttribute(proj_out_kernel,   cudaFuncAttributeMaxDynamicSharedMemorySize, GEMM_SMEM_BYTES);
    cudaFuncSetAttribute(attn_kernel, cudaFuncAttributeMaxDynamicSharedMemorySize,
                         ATT_SMEM_U * sizeof(uint32_t));

    // pack x/weights
    pack_kernel<<<dim3(256, 10), 256>>>(x0, x1, qg_w0, qg_w1,
                                        k_w0, k_w1, v_w0, v_w1, o_w0, o_w1);

    // projections (fp16), V exact to d_out + fp16 key-pair pack fused
    proj_fused_kernel<<<dim3(16, 40), 256, GEMM_SMEM_BYTES>>>(
        qg, kraw, out + VC_BASE, vph);

    // norms + rope
    qnorm_rope<<<TT*NH/4, 128>>>(qg, qh, pos, qn0, qn1);
    knorm_rope<<<TT*KH/4, 128>>>(kraw, out + KC_BASE, kph, pos, kn0, kn1);

    // attention fp16 (64-key blocks, 3 CTAs/SM)
    attn_kernel<<<dim3(TT/64, NH), 128, ATT_SMEM_U * sizeof(uint32_t)>>>(
        qh, kph, vph, qg, ench);

    // output projection (fp16)
    proj_out_kernel<<<dim3(16, 16), 256, GEMM_SMEM_BYTES>>>(out);
}